// round 7
// baseline (speedup 1.0000x reference)
#include <cuda_runtime.h>
#include <cuda_bf16.h>
#include <math.h>
#include <stdint.h>

#define Bb 32
#define Tt 1024
#define Dd 256
#define BT (Bb*Tt)
#define MAXE 64
#define NT 8
#define LN_EPS 1e-5f
#define EPS_ADJ 1e-6f
#define CAP 48
#define MARGIN 0.02f

// ---------------- device scratch ----------------
__device__ float          g_xn[BT*Dd];
__device__ __nv_bfloat16  g_xb[BT*Dd];
__device__ __nv_bfloat16  g_simb[(size_t)BT*Tt];
__device__ float          g_ahi[BT*Dd];
__device__ float          g_alo[BT*Dd];
__device__ float          g_s0[BT*Dd];
__device__ float          g_s1[BT*Dd];
__device__ float          g_whi[2*Dd*Dd];
__device__ float          g_wlo[2*Dd*Dd];
__device__ float          g_mf[BT];
__device__ int            g_top2[BT*2];
__device__ unsigned       g_bits[BT*(Tt/32)];
__device__ float          g_rinv[BT];
__device__ int            g_ecols[BT*MAXE];
__device__ float          g_evals[BT*MAXE];
__device__ int            g_ecnt[BT];
__device__ float          g_v2a[BT];

__device__ __forceinline__ uint32_t smem_to_u32(const void* p) {
    uint32_t a;
    asm("{ .reg .u64 t; cvta.to.shared.u64 t, %1; cvt.u32.u64 %0, t; }" : "=r"(a) : "l"(p));
    return a;
}
__device__ __forceinline__ void ldsm4(uint32_t& r0, uint32_t& r1, uint32_t& r2, uint32_t& r3, uint32_t addr) {
    asm volatile("ldmatrix.sync.aligned.m8n8.x4.shared.b16 {%0,%1,%2,%3}, [%4];"
                 : "=r"(r0), "=r"(r1), "=r"(r2), "=r"(r3) : "r"(addr));
}
__device__ __forceinline__ void mma_bf16(float* c, uint32_t a0, uint32_t a1, uint32_t a2, uint32_t a3,
                                         uint32_t b0, uint32_t b1) {
    asm volatile("mma.sync.aligned.m16n8k16.row.col.f32.bf16.bf16.f32 "
                 "{%0,%1,%2,%3},{%4,%5,%6,%7},{%8,%9},{%0,%1,%2,%3};"
                 : "+f"(c[0]), "+f"(c[1]), "+f"(c[2]), "+f"(c[3])
                 : "r"(a0), "r"(a1), "r"(a2), "r"(a3), "r"(b0), "r"(b1));
}
__device__ __forceinline__ void mma_tf32(float* c, uint32_t a0, uint32_t a1, uint32_t a2, uint32_t a3,
                                         uint32_t b0, uint32_t b1) {
    asm volatile("mma.sync.aligned.m16n8k8.row.col.f32.tf32.tf32.f32 "
                 "{%0,%1,%2,%3},{%4,%5,%6,%7},{%8,%9},{%0,%1,%2,%3};"
                 : "+f"(c[0]), "+f"(c[1]), "+f"(c[2]), "+f"(c[3])
                 : "r"(a0), "r"(a1), "r"(a2), "r"(a3), "r"(b0), "r"(b1));
}
__device__ __forceinline__ uint32_t to_tf32(float x) {
    uint32_t u;
    asm("cvt.rna.tf32.f32 %0, %1;" : "=r"(u) : "f"(x));
    return u;
}
#define CP_ASYNC16(dst, src) asm volatile("cp.async.cg.shared.global [%0], [%1], 16;" :: "r"(dst), "l"(src))
#define CP_COMMIT() asm volatile("cp.async.commit_group;" ::: "memory")
#define CP_WAIT0()  asm volatile("cp.async.wait_group 0;" ::: "memory")

// ---------------- normalize + mask + bf16 copy ----------------
__global__ void k_normalize(const float* __restrict__ x, const int* __restrict__ mask) {
    int row = blockIdx.x;
    int d = threadIdx.x;
    float v = x[row*Dd + d];
    __shared__ float red[8];
    float ss = v*v;
    #pragma unroll
    for (int o = 16; o; o >>= 1) ss += __shfl_xor_sync(~0u, ss, o);
    if ((threadIdx.x & 31) == 0) red[threadIdx.x >> 5] = ss;
    __syncthreads();
    if (threadIdx.x < 8) {
        float t = red[threadIdx.x];
        #pragma unroll
        for (int o = 4; o; o >>= 1) t += __shfl_xor_sync(0xff, t, o);
        if (threadIdx.x == 0) red[0] = t;
    }
    __syncthreads();
    float rn = 1.f / fmaxf(sqrtf(red[0]), 1e-12f);
    float xv = v * rn;
    g_xn[row*Dd + d] = xv;
    g_xb[row*Dd + d] = __float2bfloat16(xv);
    if (d == 0) g_mf[row] = (float)mask[row];
}

// ---------------- W hi/lo tf32 pre-split ----------------
__global__ void k_prep_w(const float* __restrict__ W0, const float* __restrict__ W1) {
    int i = blockIdx.x*256 + threadIdx.x;
    if (i < Dd*Dd) {
        float w = W0[i];
        float h = __uint_as_float(to_tf32(w));
        g_whi[i] = h;
        g_wlo[i] = __uint_as_float(to_tf32(w - h));
        w = W1[i];
        h = __uint_as_float(to_tf32(w));
        g_whi[Dd*Dd + i] = h;
        g_wlo[Dd*Dd + i] = __uint_as_float(to_tf32(w - h));
    }
}

// ============ bf16 HMMA sim + store + approx v2 (cp.async double-buffer) ============
#define PK 264
#define SMA_BYTES (128*PK*2)
#define SM_B0_OFF  SMA_BYTES
#define SM_B1_OFF  (2*SMA_BYTES)
#define SM_MASK_OFF (3*SMA_BYTES)
#define SM_TOTAL (3*SMA_BYTES + 4096)

__device__ __forceinline__ void load_tile_async(uint32_t dstb, const __nv_bfloat16* src, int tid) {
    #pragma unroll
    for (int it = 0; it < 16; it++) {
        int unit = tid + it*256;
        int row = unit >> 5;
        int c8  = (unit & 31) * 8;
        CP_ASYNC16(dstb + (uint32_t)((row*PK + c8)*2), src + row*256 + c8);
    }
}

__global__ __launch_bounds__(256, 1) void k_simtc() {
    extern __shared__ char sm[];
    float* smask = (float*)(sm + SM_MASK_OFF);
    uint32_t smbA  = smem_to_u32(sm);
    uint32_t smbB0 = smbA + SM_B0_OFF;
    uint32_t smbB1 = smbA + SM_B1_OFF;

    int b  = blockIdx.y;
    int rb = b * Tt;
    int i0 = blockIdx.x * 128;
    int tid = threadIdx.x;
    int w = tid >> 5;
    int l = tid & 31;
    int quad = l & 3;

    load_tile_async(smbA,  g_xb + (size_t)(rb + i0)*Dd, tid);
    load_tile_async(smbB0, g_xb + (size_t)rb*Dd, tid);
    CP_COMMIT();

    #pragma unroll
    for (int u = 0; u < 4; u++) smask[tid + u*256] = g_mf[rb + tid + u*256];

    int irow0 = i0 + w*16 + (l >> 2);
    int irow1 = irow0 + 8;
    float mi0 = g_mf[rb + irow0];
    float mi1 = g_mf[rb + irow1];

    uint32_t aBase = smbA + (uint32_t)(((w*16 + (l & 15))*PK + ((l >> 4) << 3)) * 2);
    uint32_t bOff  = (uint32_t)(((((l >> 4) << 3) + (l & 7))*PK + (((l >> 3) & 1) << 3)) * 2);

    float v1a = -1e30f, v2a = -1e30f, v1b = -1e30f, v2b = -1e30f;

    CP_WAIT0();
    __syncthreads();

    for (int jc = 0; jc < 8; jc++) {
        uint32_t bBase = ((jc & 1) ? smbB1 : smbB0) + bOff;
        if (jc + 1 < 8) {
            load_tile_async((jc & 1) ? smbB0 : smbB1, g_xb + (size_t)(rb + (jc+1)*128)*Dd, tid);
            CP_COMMIT();
        }

        float acc[16][4];
        #pragma unroll
        for (int n = 0; n < 16; n++)
            #pragma unroll
            for (int q = 0; q < 4; q++) acc[n][q] = 0.f;

        #pragma unroll
        for (int kk = 0; kk < 16; kk++) {
            uint32_t a0, a1, a2, a3;
            ldsm4(a0, a1, a2, a3, aBase + kk*32);
            #pragma unroll
            for (int p = 0; p < 8; p++) {
                uint32_t b0, b1, b2, b3;
                ldsm4(b0, b1, b2, b3, bBase + p*(16*PK*2) + kk*32);
                mma_bf16(acc[2*p],   a0, a1, a2, a3, b0, b1);
                mma_bf16(acc[2*p+1], a0, a1, a2, a3, b2, b3);
            }
        }

        #pragma unroll
        for (int n = 0; n < 16; n++) {
            int col = jc*128 + n*8 + quad*2;
            float s0 = acc[n][0] * mi0 * smask[col];
            float s1 = acc[n][1] * mi0 * smask[col+1];
            float s2 = acc[n][2] * mi1 * smask[col];
            float s3 = acc[n][3] * mi1 * smask[col+1];
            __nv_bfloat162 h0 = __float22bfloat162_rn(make_float2(s0, s1));
            __nv_bfloat162 h1 = __float22bfloat162_rn(make_float2(s2, s3));
            *(__nv_bfloat162*)&g_simb[(size_t)(rb + irow0)*Tt + col] = h0;
            *(__nv_bfloat162*)&g_simb[(size_t)(rb + irow1)*Tt + col] = h1;
            if (col   != irow0) { if (s0 > v1a) { v2a = v1a; v1a = s0; } else if (s0 > v2a) v2a = s0; }
            if (col+1 != irow0) { if (s1 > v1a) { v2a = v1a; v1a = s1; } else if (s1 > v2a) v2a = s1; }
            if (col   != irow1) { if (s2 > v1b) { v2b = v1b; v1b = s2; } else if (s2 > v2b) v2b = s2; }
            if (col+1 != irow1) { if (s3 > v1b) { v2b = v1b; v1b = s3; } else if (s3 > v2b) v2b = s3; }
        }
        if (jc + 1 < 8) CP_WAIT0();
        __syncthreads();
    }
    #pragma unroll
    for (int off = 1; off < 4; off <<= 1) {
        float o1 = __shfl_xor_sync(~0u, v1a, off);
        float o2 = __shfl_xor_sync(~0u, v2a, off);
        if (o1 > v1a) { v2a = fmaxf(v1a, o2); v1a = o1; } else v2a = fmaxf(v2a, o1);
        o1 = __shfl_xor_sync(~0u, v1b, off);
        o2 = __shfl_xor_sync(~0u, v2b, off);
        if (o1 > v1b) { v2b = fmaxf(v1b, o2); v1b = o1; } else v2b = fmaxf(v2b, o1);
    }
    if (quad == 0) {
        g_v2a[rb + irow0] = v2a;
        g_v2a[rb + irow1] = v2b;
    }
}

// ---------------- fused candidates + exact fp32 rescore (warp per row) ----------------
__device__ __forceinline__ bool tgt(float v, int j, float v2, int j2) {
    return (v > v2) || (v == v2 && j < j2);
}

__global__ __launch_bounds__(256) void k_candrescore() {
    __shared__ int cs[8][CAP];
    int warp = (blockIdx.x*256 + threadIdx.x) >> 5;
    int lw = (threadIdx.x >> 5) & 7;
    int lane = threadIdx.x & 31;
    if (warp >= BT) return;
    int row = warp;
    int i = row & (Tt-1);
    int b = row / Tt;
    float thr = g_v2a[row] - MARGIN;

    uint4 d[4];
    const uint4* p = (const uint4*)(g_simb + (size_t)row*Tt) + lane*4;
    #pragma unroll
    for (int t = 0; t < 4; t++) d[t] = p[t];

    int cnt = 0;
    #pragma unroll
    for (int t = 0; t < 4; t++) {
        uint32_t parts[4] = {d[t].x, d[t].y, d[t].z, d[t].w};
        #pragma unroll
        for (int h = 0; h < 4; h++) {
            float2 f = __bfloat1622float2(*(__nv_bfloat162*)&parts[h]);
            int j0 = lane*32 + t*8 + h*2;
            if (f.x >= thr && j0   != i) cnt++;
            if (f.y >= thr && j0+1 != i) cnt++;
        }
    }
    int incl = cnt;
    #pragma unroll
    for (int off = 1; off < 32; off <<= 1) {
        int n = __shfl_up_sync(~0u, incl, off);
        if (lane >= off) incl += n;
    }
    int base = incl - cnt;
    int total = __shfl_sync(~0u, incl, 31);

    int k = 0;
    #pragma unroll
    for (int t = 0; t < 4; t++) {
        uint32_t parts[4] = {d[t].x, d[t].y, d[t].z, d[t].w};
        #pragma unroll
        for (int h = 0; h < 4; h++) {
            float2 f = __bfloat1622float2(*(__nv_bfloat162*)&parts[h]);
            int j0 = lane*32 + t*8 + h*2;
            if (f.x >= thr && j0 != i) {
                int pos = base + k;
                if (pos < CAP) cs[lw][pos] = j0;
                k++;
            }
            if (f.y >= thr && j0+1 != i) {
                int pos = base + k;
                if (pos < CAP) cs[lw][pos] = j0+1;
                k++;
            }
        }
    }
    __syncwarp();
    int ccnt = min(total, CAP);

    float a[8];
    #pragma unroll
    for (int u = 0; u < 8; u++) a[u] = g_xn[row*Dd + lane + 32*u];
    float mi = g_mf[row];
    float v1 = -1e30f, v2 = -1e30f; int j1 = 0, j2 = 0;
    for (int e = 0; e < ccnt; e++) {
        int j = cs[lw][e];
        int jr = b*Tt + j;
        float dot = 0.f;
        #pragma unroll
        for (int u = 0; u < 8; u++) dot = fmaf(a[u], g_xn[jr*Dd + lane + 32*u], dot);
        #pragma unroll
        for (int o = 16; o; o >>= 1) dot += __shfl_xor_sync(~0u, dot, o);
        float s = dot * mi * g_mf[jr];
        if (tgt(s, j, v1, j1)) { v2 = v1; j2 = j1; v1 = s; j1 = j; }
        else if (tgt(s, j, v2, j2)) { v2 = s; j2 = j; }
    }
    if (lane == 0) {
        g_top2[row*2 + 0] = j1;
        g_top2[row*2 + 1] = j2;
    }
}

// ---------------- adjacency bitmap ----------------
__global__ void k_clear() {
    int i = blockIdx.x*256 + threadIdx.x;
    if (i < BT*(Tt/32)) g_bits[i] = 0u;
}

__global__ void k_setbits() {
    int row = blockIdx.x*256 + threadIdx.x;
    if (row >= BT) return;
    int b = row / Tt, i = row % Tt;
    unsigned* wb = &g_bits[row*(Tt/32)];
    atomicOr(&wb[i >> 5], 1u << (i & 31));
    if (i > 0)      atomicOr(&wb[(i-1) >> 5], 1u << ((i-1) & 31));
    if (i < Tt-1)   atomicOr(&wb[(i+1) >> 5], 1u << ((i+1) & 31));
    float mi = g_mf[row];
    #pragma unroll
    for (int t = 0; t < 2; t++) {
        int j = g_top2[row*2 + t];
        float mj = g_mf[b*Tt + j];
        if (mi*mj != 0.f) {
            atomicOr(&wb[j >> 5], 1u << (j & 31));
            atomicOr(&g_bits[(b*Tt + j)*(Tt/32) + (i >> 5)], 1u << (i & 31));
        }
    }
}

// ---------------- edge extraction (warp per row) ----------------
__global__ __launch_bounds__(256) void k_edges() {
    int warp = (blockIdx.x*256 + threadIdx.x) >> 5;
    int lane = threadIdx.x & 31;
    if (warp >= BT) return;
    int row = warp;
    int b = row / Tt, i = row % Tt;
    float a[8];
    #pragma unroll
    for (int u = 0; u < 8; u++) a[u] = g_xn[row*Dd + lane + 32*u];
    float mi = g_mf[row];
    float rowsum = 0.f;
    int cnt = 0;
    for (int w = 0; w < Tt/32; w++) {
        unsigned bitsw = g_bits[row*(Tt/32) + w];
        while (bitsw) {
            int bit = __ffs(bitsw) - 1;
            bitsw &= bitsw - 1;
            int j = w*32 + bit;
            int jr = b*Tt + j;
            float dot = 0.f;
            #pragma unroll
            for (int u = 0; u < 8; u++) dot = fmaf(a[u], g_xn[jr*Dd + lane + 32*u], dot);
            #pragma unroll
            for (int o = 16; o; o >>= 1) dot += __shfl_xor_sync(~0u, dot, o);
            float val = dot * mi * g_mf[jr];
            if (j == i) val += 1.0f;
            rowsum += val;
            if (lane == 0 && cnt < MAXE) {
                g_ecols[row*MAXE + cnt] = j;
                g_evals[row*MAXE + cnt] = val;
            }
            cnt++;
        }
    }
    if (lane == 0) {
        g_ecnt[row] = min(cnt, MAXE);
        g_rinv[row] = rsqrtf(rowsum + EPS_ADJ);
    }
}

// ---------------- sparse adj @ h, emitting tf32 hi/lo split ----------------
__global__ __launch_bounds__(256) void k_spmm(const float* __restrict__ hin) {
    int row = blockIdx.x;
    int d = threadIdx.x;
    int b = row / Tt;
    int cnt = g_ecnt[row];
    float ri = g_rinv[row], mi = g_mf[row];
    float acc = 0.f;
    for (int e = 0; e < cnt; e++) {
        int j = g_ecols[row*MAXE + e];
        int jr = b*Tt + j;
        float w = g_evals[row*MAXE + e] * ri * g_rinv[jr] * mi * g_mf[jr];
        acc = fmaf(w, hin[jr*Dd + d], acc);
    }
    float h = __uint_as_float(to_tf32(acc));
    g_ahi[row*Dd + d] = h;
    g_alo[row*Dd + d] = __uint_as_float(to_tf32(acc - h));
}

// ======== tf32 3-term HMMA (pre-split operands): A @ W^T + bias + ELU ========
#define GP 36
#define GAH 0
#define GAL (128*GP)
#define GBH (2*128*GP)
#define GBL (3*128*GP)
#define GSM_TOTAL (4*128*GP*4)

__global__ __launch_bounds__(256, 2) void k_gemm_tf32(const float* __restrict__ Ahi,
                                                      const float* __restrict__ Alo,
                                                      const float* __restrict__ Whi,
                                                      const float* __restrict__ Wlo,
                                                      const float* __restrict__ bias,
                                                      float* __restrict__ out) {
    extern __shared__ float gsmf[];
    uint32_t* gsm = (uint32_t*)gsmf;
    int r0 = blockIdx.x * 128;
    int o0 = blockIdx.y * 128;
    int tid = threadIdx.x;
    int w = tid >> 5;
    int lane = tid & 31;
    int lr = lane >> 2;
    int lc = lane & 3;

    float acc[16][4];
    #pragma unroll
    for (int n = 0; n < 16; n++)
        #pragma unroll
        for (int q = 0; q < 4; q++) acc[n][q] = 0.f;

    int m0 = w * 16;

    for (int kc = 0; kc < 8; kc++) {
        __syncthreads();
        #pragma unroll
        for (int t = 0; t < 4; t++) {
            int unit = tid + t*256;
            int row = unit >> 3;
            int k4  = (unit & 7) * 4;
            size_t ga = (size_t)(r0+row)*Dd + kc*32 + k4;
            size_t gw = (size_t)(o0+row)*Dd + kc*32 + k4;
            *(float4*)&gsmf[GAH + row*GP + k4] = *(const float4*)&Ahi[ga];
            *(float4*)&gsmf[GAL + row*GP + k4] = *(const float4*)&Alo[ga];
            *(float4*)&gsmf[GBH + row*GP + k4] = *(const float4*)&Whi[gw];
            *(float4*)&gsmf[GBL + row*GP + k4] = *(const float4*)&Wlo[gw];
        }
        __syncthreads();

        #pragma unroll
        for (int kk = 0; kk < 4; kk++) {
            int k0 = kk * 8;
            int ar = (m0 + lr) * GP + k0 + lc;
            uint32_t ah0 = gsm[GAH + ar];
            uint32_t ah1 = gsm[GAH + ar + 8*GP];
            uint32_t ah2 = gsm[GAH + ar + 4];
            uint32_t ah3 = gsm[GAH + ar + 8*GP + 4];
            uint32_t al0 = gsm[GAL + ar];
            uint32_t al1 = gsm[GAL + ar + 8*GP];
            uint32_t al2 = gsm[GAL + ar + 4];
            uint32_t al3 = gsm[GAL + ar + 8*GP + 4];
            #pragma unroll
            for (int p = 0; p < 16; p++) {
                int br = (p*8 + lr) * GP + k0 + lc;
                uint32_t bh0 = gsm[GBH + br];
                uint32_t bh1 = gsm[GBH + br + 4];
                uint32_t bl0 = gsm[GBL + br];
                uint32_t bl1 = gsm[GBL + br + 4];
                mma_tf32(acc[p], ah0, ah1, ah2, ah3, bh0, bh1);
                mma_tf32(acc[p], ah0, ah1, ah2, ah3, bl0, bl1);
                mma_tf32(acc[p], al0, al1, al2, al3, bh0, bh1);
            }
        }
    }

    #pragma unroll
    for (int p = 0; p < 16; p++) {
        int oc = o0 + p*8 + lc*2;
        float b0 = bias[oc], b1 = bias[oc+1];
        int gr0 = r0 + m0 + lr;
        float v0 = acc[p][0] + b0;
        float v1 = acc[p][1] + b1;
        float v2 = acc[p][2] + b0;
        float v3 = acc[p][3] + b1;
        v0 = (v0 > 0.f) ? v0 : expm1f(v0);
        v1 = (v1 > 0.f) ? v1 : expm1f(v1);
        v2 = (v2 > 0.f) ? v2 : expm1f(v2);
        v3 = (v3 > 0.f) ? v3 : expm1f(v3);
        *(float2*)&out[(size_t)gr0*Dd + oc]     = make_float2(v0, v1);
        *(float2*)&out[(size_t)(gr0+8)*Dd + oc] = make_float2(v2, v3);
    }
}

// ---------------- LayerNorm over D ----------------
__global__ void k_ln(const float* __restrict__ in, const float* __restrict__ g,
                     const float* __restrict__ be, float* __restrict__ out) {
    int row = blockIdx.x;
    int d = threadIdx.x;
    float v = in[row*Dd + d];
    __shared__ float red[8];

    float s = v;
    #pragma unroll
    for (int o = 16; o; o >>= 1) s += __shfl_xor_sync(~0u, s, o);
    if ((threadIdx.x & 31) == 0) red[threadIdx.x >> 5] = s;
    __syncthreads();
    if (threadIdx.x < 8) {
        float t = red[threadIdx.x];
        #pragma unroll
        for (int o = 4; o; o >>= 1) t += __shfl_xor_sync(0xff, t, o);
        if (threadIdx.x == 0) red[0] = t;
    }
    __syncthreads();
    float mu = red[0] * (1.f/Dd);
    __syncthreads();

    float dv = v - mu;
    float s2 = dv*dv;
    #pragma unroll
    for (int o = 16; o; o >>= 1) s2 += __shfl_xor_sync(~0u, s2, o);
    if ((threadIdx.x & 31) == 0) red[threadIdx.x >> 5] = s2;
    __syncthreads();
    if (threadIdx.x < 8) {
        float t = red[threadIdx.x];
        #pragma unroll
        for (int o = 4; o; o >>= 1) t += __shfl_xor_sync(0xff, t, o);
        if (threadIdx.x == 0) red[0] = t;
    }
    __syncthreads();
    float var = red[0] * (1.f/Dd);
    out[row*Dd + d] = dv * rsqrtf(var + LN_EPS) * g[d] + be[d];
}

// ---------------- launch ----------------
extern "C" void kernel_launch(void* const* d_in, const int* in_sizes, int n_in,
                              void* d_out, int out_size) {
    const float* x    = (const float*)d_in[0];
    const int*   mask = (const int*)  d_in[1];
    const float* W0 = (const float*)d_in[2];
    const float* b0 = (const float*)d_in[3];
    const float* g0 = (const float*)d_in[4];
    const float* be0= (const float*)d_in[5];
    const float* W1 = (const float*)d_in[6];
    const float* b1 = (const float*)d_in[7];
    const float* g1 = (const float*)d_in[8];
    const float* be1= (const float*)d_in[9];
    float* out = (float*)d_out;

    float *s0, *s1, *ahi, *alo, *whi, *wlo;
    cudaGetSymbolAddress((void**)&s0, g_s0);
    cudaGetSymbolAddress((void**)&s1, g_s1);
    cudaGetSymbolAddress((void**)&ahi, g_ahi);
    cudaGetSymbolAddress((void**)&alo, g_alo);
    cudaGetSymbolAddress((void**)&whi, g_whi);
    cudaGetSymbolAddress((void**)&wlo, g_wlo);

    cudaFuncSetAttribute(k_simtc, cudaFuncAttributeMaxDynamicSharedMemorySize, SM_TOTAL);
    cudaFuncSetAttribute(k_gemm_tf32, cudaFuncAttributeMaxDynamicSharedMemorySize, GSM_TOTAL);

    k_normalize<<<BT, 256>>>(x, mask);
    k_clear<<<(BT*(Tt/32) + 255)/256, 256>>>();
    k_prep_w<<<(Dd*Dd + 255)/256, 256>>>(W0, W1);
    k_simtc<<<dim3(NT, Bb), 256, SM_TOTAL>>>();
    k_candrescore<<<BT/8, 256>>>();
    k_setbits<<<BT/256, 256>>>();
    k_edges<<<(BT*32)/256, 256>>>();

    // layer 1
    k_spmm<<<BT, 256>>>(x);
    k_gemm_tf32<<<dim3(BT/128, Dd/128), 256, GSM_TOTAL>>>(ahi, alo, whi, wlo, b0, s1);
    k_ln<<<BT, 256>>>(s1, g0, be0, s0);
    // layer 2
    k_spmm<<<BT, 256>>>(s0);
    k_gemm_tf32<<<dim3(BT/128, Dd/128), 256, GSM_TOTAL>>>(ahi, alo, whi + Dd*Dd, wlo + Dd*Dd, b1, s0);
    k_ln<<<BT, 256>>>(s0, g1, be1, out);
}